// round 16
// baseline (speedup 1.0000x reference)
#include <cuda_runtime.h>
#include <math.h>

// Problem constants (fixed shapes for this problem instance)
#define S_SRC   128
#define P_PTS   2048
#define M_MIR   64
#define NCYL    16
#define NBOX    8
#define EXTENTF 12.0f
#define EPSF    1e-9f

#define TPB     256
#define SCH     32                 // sources per thread
#define CHUNKS  (S_SRC / SCH)      // 4
#define TOTAL_THREADS (M_MIR * P_PTS * CHUNKS)   // 524288
#define NBLOCKS (TOTAL_THREADS / TPB)            // 2048

__global__ __launch_bounds__(TPB)
void render_kernel(
    const float* __restrict__ sources,       // (S,3)
    const float* __restrict__ mpts,          // (M,P,3)
    const float* __restrict__ mnrm,          // (M,P,3)
    const float* __restrict__ mpos,          // (M,3)
    const float* __restrict__ mrot,          // (M,3,3)
    const float* __restrict__ cp1,           // (NC,3)
    const float* __restrict__ cp2,           // (NC,3)
    const float* __restrict__ crad,          // (NC,)
    const float* __restrict__ bp1,           // (NB,3)
    const float* __restrict__ bp2,           // (NB,3)
    const float* __restrict__ spos,          // (3,)
    const float* __restrict__ snrm,          // (3,)
    const int*   __restrict__ hptr,          // scalar sensor_h
    const int*   __restrict__ wptr,          // scalar sensor_w
    float* __restrict__ out,
    int out_size)
{
    __shared__ float4 s_src[S_SRC];    // x,y,z,0
    __shared__ float4 s_cylA[NCYL];    // unit-ish axis a.xyz, L
    __shared__ float4 s_cylP[NCYL];    // p1.xyz, r^2
    __shared__ float4 s_boxLo[NBOX];   // p1.xyz, 0
    __shared__ float4 s_boxHi[NBOX];   // p2.xyz, 0

    const int tid = threadIdx.x;

    // ---- prologue: stage small geometry into shared memory ----
    if (tid < S_SRC) {
        s_src[tid] = make_float4(sources[tid*3+0], sources[tid*3+1], sources[tid*3+2], 0.0f);
    } else if (tid < S_SRC + NCYL) {
        int c = tid - S_SRC;
        float ax = cp2[c*3+0] - cp1[c*3+0];
        float ay = cp2[c*3+1] - cp1[c*3+1];
        float az = cp2[c*3+2] - cp1[c*3+2];
        float L  = sqrtf(ax*ax + ay*ay + az*az);
        float Le = L + EPSF;
        // match reference: a = axis / (L + EPS)
        s_cylA[c] = make_float4(ax / Le, ay / Le, az / Le, L);
        float r = crad[c];
        s_cylP[c] = make_float4(cp1[c*3+0], cp1[c*3+1], cp1[c*3+2], r*r);
    } else if (tid < S_SRC + NCYL + NBOX) {
        int b = tid - S_SRC - NCYL;
        s_boxLo[b] = make_float4(bp1[b*3+0], bp1[b*3+1], bp1[b*3+2], 0.0f);
        s_boxHi[b] = make_float4(bp2[b*3+0], bp2[b*3+1], bp2[b*3+2], 0.0f);
    }
    __syncthreads();

    // ---- thread identity: (mirror m, point p, source chunk ch) ----
    const int gt = blockIdx.x * TPB + tid;
    const int ch = gt & (CHUNKS - 1);
    const int mp = gt >> 2;              // log2(CHUNKS) = 2
    const int m  = mp >> 11;             // log2(P_PTS)  = 11

    // rotate mirror point + normal (tp_all / tn_all computed inline)
    const float px = mpts[mp*3+0], py = mpts[mp*3+1], pz = mpts[mp*3+2];
    const float ux = mnrm[mp*3+0], uy = mnrm[mp*3+1], uz = mnrm[mp*3+2];
    const float* R = mrot + m*9;
    const float r00=R[0], r01=R[1], r02=R[2];
    const float r10=R[3], r11=R[4], r12=R[5];
    const float r20=R[6], r21=R[7], r22=R[8];

    const float ox = r00*px + r01*py + r02*pz + mpos[m*3+0];
    const float oy = r10*px + r11*py + r12*pz + mpos[m*3+1];
    const float oz = r20*px + r21*py + r22*pz + mpos[m*3+2];
    const float nx = r00*ux + r01*uy + r02*uz;
    const float ny = r10*ux + r11*uy + r12*uz;
    const float nz = r20*ux + r21*uy + r22*uz;

    const float npx = snrm[0], npy = snrm[1], npz = snrm[2];
    const float Tnum = (spos[0]-ox)*npx + (spos[1]-oy)*npy + (spos[2]-oz)*npz;

    // sensor dims (guarded dynamic read, fall back to 512x512)
    int Wd = 512, Hd = 512;
    if (wptr) { int w = *wptr; if (w > 0 && w <= 65536) Wd = w; }
    if (hptr) { int h = *hptr; if (h > 0 && h <= 65536) Hd = h; }
    if (Wd * Hd != out_size) { Wd = 512; Hd = 512; }
    const float Wf = (float)Wd, Hf = (float)Hd;
    const float sW = Wf / (2.0f * EXTENTF);
    const float sH = Hf / (2.0f * EXTENTF);

    const float4* srcc = s_src + ch * SCH;

    // ---- phase 1: cylinder occlusion, per-source hit bitmask ----
    // Work with unnormalized ray w = src - o. All t/axial conditions are
    // multiplied through by the positive denominator, so no divisions and
    // no per-(cyl,src) normalization are needed; signs match the reference.
    unsigned mask = 0u;
    #pragma unroll 1
    for (int c = 0; c < NCYL; ++c) {
        const float4 ca = s_cylA[c];
        const float4 cp = s_cylP[c];
        const float ocx = ox - cp.x, ocy = oy - cp.y, ocz = oz - cp.z;
        const float oa  = ocx*ca.x + ocy*ca.y + ocz*ca.z;
        const float mxx = ocx - oa*ca.x;
        const float myy = ocy - oa*ca.y;
        const float mzz = ocz - oa*ca.z;
        const float Cc  = mxx*mxx + myy*myy + mzz*mzz - cp.w;

        #pragma unroll 4
        for (int s = 0; s < SCH; ++s) {
            const float4 sv = srcc[s];
            const float wx = sv.x - ox, wy = sv.y - oy, wz = sv.z - oz;
            const float wa = wx*ca.x + wy*ca.y + wz*ca.z;
            const float dx = wx - wa*ca.x;
            const float dy = wy - wa*ca.y;
            const float dz = wz - wa*ca.z;
            const float A  = dx*dx + dy*dy + dz*dz;
            const float B  = 2.0f * (mxx*dx + myy*dy + mzz*dz);
            const float disc = B*B - 4.0f*A*Cc;
            const float sq = sqrtf(fmaxf(disc, 0.0f));
            const float D   = 2.0f*A + EPSF;      // > 0
            const float oaD = oa * D;
            const float LD  = ca.w * D;
            const float n1 = -B - sq, n2 = -B + sq;
            const float e1 = oaD + wa*n1;
            const float e2 = oaD + wa*n2;
            const bool h1 = (n1 > 0.0f) && (e1 >= 0.0f) && (e1 <= LD);
            const bool h2 = (n2 > 0.0f) && (e2 >= 0.0f) && (e2 <= LD);
            const bool hit = (disc > 0.0f) && (h1 || h2);
            mask |= hit ? (1u << s) : 0u;
        }
    }

    // ---- phase 2: box occlusion + reflection + scatter ----
    #pragma unroll 1
    for (int s = 0; s < SCH; ++s) {
        const float4 sv = srcc[s];
        const float wx = sv.x - ox, wy = sv.y - oy, wz = sv.z - oz;
        const float d2  = wx*wx + wy*wy + wz*wz;
        const float len = sqrtf(d2);
        const float el  = EPSF * len;     // EPS threshold in w-space

        // reference clamps |u_i| < EPS -> +EPS (u = w/len)
        const float cx = (fabsf(wx) < el) ? el : wx;
        const float cy = (fabsf(wy) < el) ? el : wy;
        const float cz = (fabsf(wz) < el) ? el : wz;
        const float ivx = 1.0f / cx;
        const float ivy = 1.0f / cy;
        const float ivz = 1.0f / cz;

        bool hitb = false;
        #pragma unroll
        for (int b = 0; b < NBOX; ++b) {
            const float4 lo = s_boxLo[b];
            const float4 hi = s_boxHi[b];
            const float tax = (lo.x - ox)*ivx, tbx = (hi.x - ox)*ivx;
            const float tay = (lo.y - oy)*ivy, tby = (hi.y - oy)*ivy;
            const float taz = (lo.z - oz)*ivz, tbz = (hi.z - oz)*ivz;
            const float tmin = fmaxf(fmaxf(fminf(tax,tbx), fminf(tay,tby)), fminf(taz,tbz));
            const float tmax = fminf(fminf(fmaxf(tax,tbx), fmaxf(tay,tby)), fmaxf(taz,tbz));
            hitb = hitb || (tmax >= fmaxf(tmin, EPSF));
        }

        // reflection toward sensor plane.  d = -w/len, u = w/len.
        const float swn = wx*nx + wy*ny + wz*nz;       // = -len * (d . n)
        const float invlen = 1.0f / len;
        const float v = fabsf(swn) * invlen;           // cos(theta)
        const float rwx = 2.0f*swn*nx - wx;            // len * refl
        const float rwy = 2.0f*swn*ny - wy;
        const float rwz = 2.0f*swn*nz - wz;
        const float dm = rwx*npx + rwy*npy + rwz*npz;  // len * denom
        const float g  = Tnum / (dm + el);             // == t/len
        const float qx = ox + g*rwx;
        const float qy = oy + g*rwy;

        const float fx = (qx + EXTENTF) * sW;
        const float fy = (qy + EXTENTF) * sH;

        const bool lit = (((mask >> s) & 1u) == 0u) && !hitb;
        const bool inb = (fx >= 0.0f) && (fx < Wf) && (fy >= 0.0f) && (fy < Hf);
        if (lit && inb) {
            const int ix = (int)fx;     // fx >= 0 -> trunc == floor
            const int iy = (int)fy;
            atomicAdd(out + iy*Wd + ix, v);
        }
    }
}

extern "C" void kernel_launch(void* const* d_in, const int* in_sizes, int n_in,
                              void* d_out, int out_size)
{
    (void)in_sizes;
    // output is poisoned to 0xAA before timing -> zero it every launch
    cudaMemsetAsync(d_out, 0, (size_t)out_size * sizeof(float), 0);

    const int* hptr = (n_in > 12) ? (const int*)d_in[12] : nullptr;
    const int* wptr = (n_in > 13) ? (const int*)d_in[13] : nullptr;

    render_kernel<<<NBLOCKS, TPB>>>(
        (const float*)d_in[0],   // sources
        (const float*)d_in[1],   // mirror_points
        (const float*)d_in[2],   // mirror_normals
        (const float*)d_in[3],   // mirror_positions
        (const float*)d_in[4],   // mirror_rotations
        (const float*)d_in[5],   // cyl_p1
        (const float*)d_in[6],   // cyl_p2
        (const float*)d_in[7],   // cyl_radius
        (const float*)d_in[8],   // box_p1
        (const float*)d_in[9],   // box_p2
        (const float*)d_in[10],  // sensor_plane_pos
        (const float*)d_in[11],  // sensor_plane_normal
        hptr, wptr,
        (float*)d_out, out_size);
}

// round 17
// speedup vs baseline: 6.6061x; 6.6061x over previous
#include <cuda_runtime.h>
#include <math.h>

// Problem constants (fixed shapes for this problem instance)
#define S_SRC   128
#define P_PTS   2048
#define M_MIR   64
#define NCYL    16
#define NBOX    8
#define EXTENTF 12.0f
#define EPSF    1e-9f

#define TPB     256
#define SCH     32                 // sources per thread
#define CHUNKS  (S_SRC / SCH)      // 4
#define MP_TOTAL (M_MIR * P_PTS)                 // 131072 = 2^17
#define TOTAL_THREADS (MP_TOTAL * CHUNKS)        // 524288
#define NBLOCKS (TOTAL_THREADS / TPB)            // 2048

__global__ __launch_bounds__(TPB)
void render_kernel(
    const float* __restrict__ sources,       // (S,3)
    const float* __restrict__ mpts,          // (M,P,3)
    const float* __restrict__ mnrm,          // (M,P,3)
    const float* __restrict__ mpos,          // (M,3)
    const float* __restrict__ mrot,          // (M,3,3)
    const float* __restrict__ cp1,           // (NC,3)
    const float* __restrict__ cp2,           // (NC,3)
    const float* __restrict__ crad,          // (NC,)
    const float* __restrict__ bp1,           // (NB,3)
    const float* __restrict__ bp2,           // (NB,3)
    const float* __restrict__ spos,          // (3,)
    const float* __restrict__ snrm,          // (3,)
    const int*   __restrict__ hptr,          // scalar sensor_h
    const int*   __restrict__ wptr,          // scalar sensor_w
    float* __restrict__ out,
    int out_size)
{
    __shared__ float4 s_src[S_SRC];    // x,y,z,0
    __shared__ float4 s_cylA[NCYL];    // unit-ish axis a.xyz, L
    __shared__ float4 s_cylP[NCYL];    // p1.xyz, r^2
    __shared__ float4 s_cylC[NCYL];    // cull: axis xy, r, z1eff (INF => never cull)
    __shared__ float4 s_boxLo[NBOX];
    __shared__ float4 s_boxHi[NBOX];
    __shared__ float  s_meta[5];       // src bbox: xmin,xmax,ymin,ymax,zmin

    const int tid = threadIdx.x;

    // ---- source bbox (warp 0) ----
    if (tid < 32) {
        float mnx =  INFINITY, mxx = -INFINITY;
        float mny =  INFINITY, mxy = -INFINITY;
        float mnz =  INFINITY;
        for (int i = tid; i < S_SRC; i += 32) {
            float x = sources[i*3+0], y = sources[i*3+1], z = sources[i*3+2];
            mnx = fminf(mnx, x); mxx = fmaxf(mxx, x);
            mny = fminf(mny, y); mxy = fmaxf(mxy, y);
            mnz = fminf(mnz, z);
        }
        #pragma unroll
        for (int o = 16; o; o >>= 1) {
            mnx = fminf(mnx, __shfl_xor_sync(0xffffffff, mnx, o));
            mxx = fmaxf(mxx, __shfl_xor_sync(0xffffffff, mxx, o));
            mny = fminf(mny, __shfl_xor_sync(0xffffffff, mny, o));
            mxy = fmaxf(mxy, __shfl_xor_sync(0xffffffff, mxy, o));
            mnz = fminf(mnz, __shfl_xor_sync(0xffffffff, mnz, o));
        }
        if (tid == 0) {
            s_meta[0] = mnx; s_meta[1] = mxx;
            s_meta[2] = mny; s_meta[3] = mxy;
            s_meta[4] = mnz;
        }
    }

    // ---- stage small geometry into shared memory ----
    if (tid < S_SRC) {
        s_src[tid] = make_float4(sources[tid*3+0], sources[tid*3+1], sources[tid*3+2], 0.0f);
    } else if (tid < S_SRC + NCYL) {
        int c = tid - S_SRC;
        float p1x = cp1[c*3+0], p1y = cp1[c*3+1], p1z = cp1[c*3+2];
        float p2z = cp2[c*3+2];
        float ax = cp2[c*3+0] - p1x;
        float ay = cp2[c*3+1] - p1y;
        float az = p2z - p1z;
        float L  = sqrtf(ax*ax + ay*ay + az*az);
        float Le = L + EPSF;
        s_cylA[c] = make_float4(ax / Le, ay / Le, az / Le, L);
        float r = crad[c];
        s_cylP[c] = make_float4(p1x, p1y, p1z, r*r);
        // culling is only valid for (near-)vertical cylinders; otherwise disable
        bool vert = (ax == 0.0f) && (ay == 0.0f) && (fabsf(az) > 1e-6f);
        float z1 = vert ? (fmaxf(p1z, p2z) + 1e-5f) : INFINITY;
        s_cylC[c] = make_float4(p1x, p1y, r, z1);
    } else if (tid < S_SRC + NCYL + NBOX) {
        int b = tid - S_SRC - NCYL;
        s_boxLo[b] = make_float4(bp1[b*3+0], bp1[b*3+1], bp1[b*3+2], 0.0f);
        s_boxHi[b] = make_float4(bp2[b*3+0], bp2[b*3+1], bp2[b*3+2], 0.0f);
    }
    __syncthreads();

    // ---- thread identity: (mirror m, point p, source chunk ch) ----
    // chunk index in the HIGH bits so every warp lane shares one source
    // chunk (shared loads become pure broadcasts, no bank conflicts).
    const int gt = blockIdx.x * TPB + tid;
    const int mp = gt & (MP_TOTAL - 1);
    const int ch = gt >> 17;             // log2(MP_TOTAL) = 17
    const int m  = mp >> 11;             // log2(P_PTS)  = 11

    // rotate mirror point + normal
    const float px = mpts[mp*3+0], py = mpts[mp*3+1], pz = mpts[mp*3+2];
    const float ux = mnrm[mp*3+0], uy = mnrm[mp*3+1], uz = mnrm[mp*3+2];
    const float* R = mrot + m*9;
    const float r00=R[0], r01=R[1], r02=R[2];
    const float r10=R[3], r11=R[4], r12=R[5];
    const float r20=R[6], r21=R[7], r22=R[8];

    const float ox = r00*px + r01*py + r02*pz + mpos[m*3+0];
    const float oy = r10*px + r11*py + r12*pz + mpos[m*3+1];
    const float oz = r20*px + r21*py + r22*pz + mpos[m*3+2];
    const float nx = r00*ux + r01*uy + r02*uz;
    const float ny = r10*ux + r11*uy + r12*uz;
    const float nz = r20*ux + r21*uy + r22*uz;

    const float npx = snrm[0], npy = snrm[1], npz = snrm[2];
    const float Tnum = (spos[0]-ox)*npx + (spos[1]-oy)*npy + (spos[2]-oz)*npz;

    // sensor dims (guarded dynamic read, fall back to 512x512)
    int Wd = 512, Hd = 512;
    if (wptr) { int w = *wptr; if (w > 0 && w <= 65536) Wd = w; }
    if (hptr) { int h = *hptr; if (h > 0 && h <= 65536) Hd = h; }
    if (Wd * Hd != out_size) { Wd = 512; Hd = 512; }
    const float Wf = (float)Wd, Hf = (float)Hd;
    const float sW = Wf / (2.0f * EXTENTF);
    const float sH = Hf / (2.0f * EXTENTF);

    const float4* srcc = s_src + ch * SCH;

    // ---- conservative occluder culling ----
    // All shadow rays go from o toward a source. For any obstacle slab
    // z <= z1, the ray's xy deviation from o_xy is bounded by
    //   (z1 - oz)/(sz_min - oz) * max_s |s_xy - o_xy|.
    // Valid whenever every source is well above o (cullok); margins cover
    // fp rounding and the reference's EPS terms. Culling only ever REMOVES
    // obstacles the exact test would reject, so results are unchanged.
    const float bx0 = s_meta[0], bx1 = s_meta[1];
    const float by0 = s_meta[2], by1 = s_meta[3];
    const float szmin = s_meta[4];
    const float dxm = fmaxf(fabsf(ox - bx0), fabsf(ox - bx1));
    const float dym = fmaxf(fabsf(oy - by0), fabsf(oy - by1));
    const float Dmax = sqrtf(dxm*dxm + dym*dym);
    const float dzs = szmin - oz;
    const bool  cullok = (dzs > 0.5f);
    const float reachk = cullok ? (Dmax * 1.0001f / dzs) : 0.0f;

    unsigned cmask = 0u;
    #pragma unroll
    for (int c = 0; c < NCYL; ++c) {
        const float4 cc = s_cylC[c];
        const float ddx = ox - cc.x, ddy = oy - cc.y;
        const float dist2 = ddx*ddx + ddy*ddy;
        const float zr = fminf(fmaxf(cc.w - oz, 0.0f), 1e18f);
        const float reach = cc.z + zr*reachk + 1e-3f;
        const bool keep = (!cullok) || (dist2 <= reach*reach);
        if (keep) cmask |= (1u << c);
    }
    const unsigned wcyl = __reduce_or_sync(0xffffffff, cmask);

    unsigned bmask = 0u;
    #pragma unroll
    for (int b = 0; b < NBOX; ++b) {
        const float4 lo = s_boxLo[b];
        const float4 hi = s_boxHi[b];
        const float ddx = fmaxf(fmaxf(lo.x - ox, ox - hi.x), 0.0f);
        const float ddy = fmaxf(fmaxf(lo.y - oy, oy - hi.y), 0.0f);
        const float zr = fminf(fmaxf(hi.z - oz, 0.0f), 1e18f);
        const float reach = zr*reachk + 1e-3f;
        const bool keep = (!cullok) || (ddx*ddx + ddy*ddy <= reach*reach);
        if (keep) bmask |= (1u << b);
    }
    const unsigned wbox = __reduce_or_sync(0xffffffff, bmask);

    // ---- phase 1: cylinder occlusion over surviving cylinders ----
    unsigned mask = 0u;
    unsigned cm = wcyl;
    while (cm) {
        const int c = __ffs(cm) - 1;
        cm &= cm - 1;
        const float4 ca = s_cylA[c];
        const float4 cp = s_cylP[c];
        const float ocx = ox - cp.x, ocy = oy - cp.y, ocz = oz - cp.z;
        const float oa  = ocx*ca.x + ocy*ca.y + ocz*ca.z;
        const float mxx = ocx - oa*ca.x;
        const float myy = ocy - oa*ca.y;
        const float mzz = ocz - oa*ca.z;
        const float Cc  = mxx*mxx + myy*myy + mzz*mzz - cp.w;

        #pragma unroll 4
        for (int s = 0; s < SCH; ++s) {
            const float4 sv = srcc[s];
            const float wx = sv.x - ox, wy = sv.y - oy, wz = sv.z - oz;
            const float wa = wx*ca.x + wy*ca.y + wz*ca.z;
            const float dx = wx - wa*ca.x;
            const float dy = wy - wa*ca.y;
            const float dz = wz - wa*ca.z;
            const float A  = dx*dx + dy*dy + dz*dz;
            const float B  = 2.0f * (mxx*dx + myy*dy + mzz*dz);
            const float disc = B*B - 4.0f*A*Cc;
            const float sq = sqrtf(fmaxf(disc, 0.0f));
            const float D   = 2.0f*A + EPSF;      // > 0
            const float oaD = oa * D;
            const float LD  = ca.w * D;
            const float n1 = -B - sq, n2 = -B + sq;
            const float e1 = oaD + wa*n1;
            const float e2 = oaD + wa*n2;
            const bool h1 = (n1 > 0.0f) && (e1 >= 0.0f) && (e1 <= LD);
            const bool h2 = (n2 > 0.0f) && (e2 >= 0.0f) && (e2 <= LD);
            const bool hit = (disc > 0.0f) && (h1 || h2);
            mask |= hit ? (1u << s) : 0u;
        }
    }

    // ---- phase 2: box occlusion + reflection + scatter ----
    #pragma unroll 1
    for (int s = 0; s < SCH; ++s) {
        const float4 sv = srcc[s];
        const float wx = sv.x - ox, wy = sv.y - oy, wz = sv.z - oz;
        const float d2  = wx*wx + wy*wy + wz*wz;
        const float len = sqrtf(d2);
        const float el  = EPSF * len;     // EPS threshold in w-space

        bool hitb = false;
        unsigned bm = wbox;               // warp-uniform
        if (bm) {
            // reference clamps |u_i| < EPS -> +EPS (u = w/len)
            const float cx = (fabsf(wx) < el) ? el : wx;
            const float cy = (fabsf(wy) < el) ? el : wy;
            const float cz = (fabsf(wz) < el) ? el : wz;
            const float ivx = 1.0f / cx;
            const float ivy = 1.0f / cy;
            const float ivz = 1.0f / cz;
            do {
                const int b = __ffs(bm) - 1;
                bm &= bm - 1;
                const float4 lo = s_boxLo[b];
                const float4 hi = s_boxHi[b];
                const float tax = (lo.x - ox)*ivx, tbx = (hi.x - ox)*ivx;
                const float tay = (lo.y - oy)*ivy, tby = (hi.y - oy)*ivy;
                const float taz = (lo.z - oz)*ivz, tbz = (hi.z - oz)*ivz;
                const float tmin = fmaxf(fmaxf(fminf(tax,tbx), fminf(tay,tby)), fminf(taz,tbz));
                const float tmax = fminf(fminf(fmaxf(tax,tbx), fmaxf(tay,tby)), fmaxf(taz,tbz));
                hitb = hitb || (tmax >= fmaxf(tmin, EPSF));
            } while (bm);
        }

        // reflection toward sensor plane.  d = -w/len, u = w/len.
        const float swn = wx*nx + wy*ny + wz*nz;       // = -len * (d . n)
        const float invlen = 1.0f / len;
        const float v = fabsf(swn) * invlen;           // cos(theta)
        const float rwx = 2.0f*swn*nx - wx;            // len * refl
        const float rwy = 2.0f*swn*ny - wy;
        const float rwz = 2.0f*swn*nz - wz;
        const float dm = rwx*npx + rwy*npy + rwz*npz;  // len * denom
        const float g  = Tnum / (dm + el);             // == t/len
        const float qx = ox + g*rwx;
        const float qy = oy + g*rwy;

        const float fx = (qx + EXTENTF) * sW;
        const float fy = (qy + EXTENTF) * sH;

        const bool lit = (((mask >> s) & 1u) == 0u) && !hitb;
        const bool inb = (fx >= 0.0f) && (fx < Wf) && (fy >= 0.0f) && (fy < Hf);
        if (lit && inb) {
            const int ix = (int)fx;     // fx >= 0 -> trunc == floor
            const int iy = (int)fy;
            atomicAdd(out + iy*Wd + ix, v);
        }
    }
}

extern "C" void kernel_launch(void* const* d_in, const int* in_sizes, int n_in,
                              void* d_out, int out_size)
{
    (void)in_sizes;
    // output is poisoned to 0xAA before timing -> zero it every launch
    cudaMemsetAsync(d_out, 0, (size_t)out_size * sizeof(float), 0);

    const int* hptr = (n_in > 12) ? (const int*)d_in[12] : nullptr;
    const int* wptr = (n_in > 13) ? (const int*)d_in[13] : nullptr;

    render_kernel<<<NBLOCKS, TPB>>>(
        (const float*)d_in[0],   // sources
        (const float*)d_in[1],   // mirror_points
        (const float*)d_in[2],   // mirror_normals
        (const float*)d_in[3],   // mirror_positions
        (const float*)d_in[4],   // mirror_rotations
        (const float*)d_in[5],   // cyl_p1
        (const float*)d_in[6],   // cyl_p2
        (const float*)d_in[7],   // cyl_radius
        (const float*)d_in[8],   // box_p1
        (const float*)d_in[9],   // box_p2
        (const float*)d_in[10],  // sensor_plane_pos
        (const float*)d_in[11],  // sensor_plane_normal
        hptr, wptr,
        (float*)d_out, out_size);
}